// round 1
// baseline (speedup 1.0000x reference)
#include <cuda_runtime.h>
#include <math.h>

#define BB   64
#define VV   2048
#define ENCD 128
#define TT   100
#define EMBD 256
#define DECD 512
#define ATTD 256
#define NVOC 29
#define XD   384   // EMB + ENC

#define PRED_OFF  0
#define ALPHA_OFF (BB*TT*NVOC)            // 185600
#define LEN_OFF   (ALPHA_OFF + BB*TT*VV)  // 13292800

// ---------------- scratch (device globals; no allocation allowed) ----------
__device__ float g_enc_att[BB*VV*ATTD];   // 128 MB: enc @ W_enc.T + b_enc
__device__ float g_hbuf[2][BB*DECD];      // ping-pong h
__device__ float g_c[BB*DECD];
__device__ float g_dec_att[BB*ATTD];
__device__ float g_gate[BB*ENCD];
__device__ float g_scores[BB*VV];
__device__ float g_x[BB*XD];              // [emb_t , gate*awe]

__device__ __forceinline__ float sigf(float x) { return 1.f/(1.f+__expf(-x)); }

// ============================================================================
// Setup A: mean_enc -> h0,c0 ; write caption_lengths to out tail
// grid(64), block(512)
// ============================================================================
__global__ void s_init(const float* __restrict__ enc, const int* __restrict__ lens,
                       const float* __restrict__ Wih_, const float* __restrict__ bih_,
                       const float* __restrict__ Wic_, const float* __restrict__ bic_,
                       float* __restrict__ out)
{
    int b = blockIdx.x, tid = threadIdx.x;
    __shared__ float red[16*128];
    __shared__ float mean[128];
    int vr = tid >> 5, l = tid & 31;

    float4 acc = make_float4(0.f,0.f,0.f,0.f);
    for (int v = vr; v < VV; v += 16) {
        float4 e = *(const float4*)&enc[((size_t)(b*VV + v))*ENCD + l*4];
        acc.x += e.x; acc.y += e.y; acc.z += e.z; acc.w += e.w;
    }
    *(float4*)&red[vr*128 + l*4] = acc;
    __syncthreads();
    if (tid < 128) {
        float s = 0.f;
        #pragma unroll
        for (int i = 0; i < 16; i++) s += red[i*128 + tid];
        mean[tid] = s * (1.f/(float)VV);
    }
    __syncthreads();
    // h0, c0 : tid = j
    float ha = bih_[tid], ca = bic_[tid];
    const float* wh = Wih_ + (size_t)tid*ENCD;
    const float* wc = Wic_ + (size_t)tid*ENCD;
    #pragma unroll 4
    for (int k = 0; k < ENCD; k++) {
        float mk = mean[k];
        ha += mk * wh[k];
        ca += mk * wc[k];
    }
    g_hbuf[0][b*DECD + tid] = ha;
    g_c[b*DECD + tid] = ca;
    if (tid == 0) out[LEN_OFF + b] = (float)lens[b];
}

// ============================================================================
// Setup B: enc_att = enc @ W_enc.T + b_enc   (M=131072, N=256, K=128)
// grid(4096), block(256), dyn smem ~166KB.  4x8 register tile per thread.
// ============================================================================
#define EA_SMEM ((128*264 + 128*68)*4)
__global__ void __launch_bounds__(256)
s_encatt(const float* __restrict__ enc, const float* __restrict__ Wenc,
         const float* __restrict__ benc)
{
    extern __shared__ float sm[];
    float* Wt = sm;             // [128][264] : Wt[k][a]
    float* Et = sm + 128*264;   // [128][68]  : Et[k][r]
    int tid = threadIdx.x;
    int rowbase = blockIdx.x * 32;   // linear (b*V+v) row

    for (int i = tid; i < 256*128; i += 256) {
        int k = i & 127, a = i >> 7;
        Wt[k*264 + a] = Wenc[a*128 + k];
    }
    for (int i = tid; i < 32*128; i += 256) {
        int k = i & 127, r = i >> 7;
        Et[k*68 + r] = enc[(size_t)(rowbase + r)*128 + k];
    }
    __syncthreads();

    int tr = tid >> 5, ta = tid & 31;
    int r0 = tr*4, a0 = ta*8;
    float acc[4][8];
    #pragma unroll
    for (int i = 0; i < 4; i++)
        #pragma unroll
        for (int j = 0; j < 8; j++) acc[i][j] = 0.f;

    #pragma unroll 4
    for (int k = 0; k < 128; k++) {
        float4 rf = *(const float4*)&Et[k*68 + r0];
        float4 a4 = *(const float4*)&Wt[k*264 + a0];
        float4 b4 = *(const float4*)&Wt[k*264 + a0 + 4];
        float rr[4] = {rf.x, rf.y, rf.z, rf.w};
        float aa[8] = {a4.x,a4.y,a4.z,a4.w,b4.x,b4.y,b4.z,b4.w};
        #pragma unroll
        for (int i = 0; i < 4; i++)
            #pragma unroll
            for (int j = 0; j < 8; j++) acc[i][j] += rr[i]*aa[j];
    }
    float4 be0 = *(const float4*)&benc[a0];
    float4 be1 = *(const float4*)&benc[a0+4];
    #pragma unroll
    for (int i = 0; i < 4; i++) {
        size_t base = (size_t)(rowbase + r0 + i)*ATTD + a0;
        float4 o0 = make_float4(acc[i][0]+be0.x, acc[i][1]+be0.y, acc[i][2]+be0.z, acc[i][3]+be0.w);
        float4 o1 = make_float4(acc[i][4]+be1.x, acc[i][5]+be1.y, acc[i][6]+be1.z, acc[i][7]+be1.w);
        *(float4*)&g_enc_att[base]     = o0;
        *(float4*)&g_enc_att[base + 4] = o1;
    }
}

// ============================================================================
// K1: dec_att = h@W_dec.T+b ; gate = sig(h@W_beta.T+b) ; pred_{t-1}=h@W_final.T+b
// 416 logical rows x 64 b.  grid(26,4), block(256) = 16 rows x 16 b-lanes.
// Weight read once per 16-b group; h staged in smem transposed.
// ============================================================================
__global__ void __launch_bounds__(256)
k1_head(int t,
        const float* __restrict__ Wdec, const float* __restrict__ bdec,
        const float* __restrict__ Wbeta, const float* __restrict__ bbeta,
        const float* __restrict__ Wfin, const float* __restrict__ bfin,
        const int* __restrict__ lens, float* __restrict__ out)
{
    __shared__ float hT[512*17];
    int tid = threadIdx.x;
    int p = t & 1;
    int bg = blockIdx.y;
    int rr = blockIdx.x*16 + (tid >> 4);
    int lane = tid & 15;
    int b = bg*16 + lane;

    const float* hsrc = g_hbuf[p];
    for (int i = tid; i < 16*512; i += 256) {
        int bl = i >> 9, k = i & 511;
        hT[k*17 + bl] = hsrc[(bg*16 + bl)*DECD + k];
    }
    __syncthreads();

    const float* wrow = nullptr; float bias = 0.f;
    if (rr < 256)      { wrow = Wdec  + (size_t)rr*DECD;       bias = bdec[rr]; }
    else if (rr < 384) { wrow = Wbeta + (size_t)(rr-256)*DECD; bias = bbeta[rr-256]; }
    else if (rr < 384+NVOC) { wrow = Wfin + (size_t)(rr-384)*DECD; bias = bfin[rr-384]; }

    if (wrow) {
        float acc = bias;
        #pragma unroll 4
        for (int k = 0; k < 512; k += 4) {
            float4 w = *(const float4*)&wrow[k];
            acc += w.x*hT[(k  )*17 + lane] + w.y*hT[(k+1)*17 + lane]
                 + w.z*hT[(k+2)*17 + lane] + w.w*hT[(k+3)*17 + lane];
        }
        if (rr < 256) {
            g_dec_att[b*ATTD + rr] = acc;
        } else if (rr < 384) {
            g_gate[b*ENCD + (rr-256)] = sigf(acc);
        } else {
            if (t > 0 && (t-1) < lens[b])
                out[PRED_OFF + ((size_t)b*TT + (t-1))*NVOC + (rr-384)] = acc;
        }
    }
}

// ============================================================================
// K2: scores[b,v] = sum_a relu(enc_att[b,v,a] + dec_att[b,a]) * w_full[a]
// (b_full dropped: softmax shift-invariant).  grid(16,64), block(256)=8 warps.
// Length-masked: skips entire b.  HBM-streaming over enc_att.
// ============================================================================
__global__ void __launch_bounds__(256)
k2_scores(int t, const float* __restrict__ wfull, const int* __restrict__ lens)
{
    int b = blockIdx.y;
    if (t >= lens[b]) return;
    int warp = threadIdx.x >> 5, l = threadIdx.x & 31;
    int a0 = l*8;
    float4 d0 = *(const float4*)&g_dec_att[b*ATTD + a0];
    float4 d1 = *(const float4*)&g_dec_att[b*ATTD + a0 + 4];
    float4 w0 = *(const float4*)&wfull[a0];
    float4 w1 = *(const float4*)&wfull[a0 + 4];
    int vbase = blockIdx.x*128;

    #pragma unroll 2
    for (int i = 0; i < 16; i += 2) {
        int v0 = vbase + warp + i*8;
        int v1 = v0 + 8;
        const float4* p0 = (const float4*)&g_enc_att[((size_t)(b*VV + v0))*ATTD + a0];
        const float4* p1 = (const float4*)&g_enc_att[((size_t)(b*VV + v1))*ATTD + a0];
        float4 e00 = p0[0], e01 = p0[1];
        float4 e10 = p1[0], e11 = p1[1];

        float s0 = fmaxf(e00.x+d0.x,0.f)*w0.x + fmaxf(e00.y+d0.y,0.f)*w0.y
                 + fmaxf(e00.z+d0.z,0.f)*w0.z + fmaxf(e00.w+d0.w,0.f)*w0.w
                 + fmaxf(e01.x+d1.x,0.f)*w1.x + fmaxf(e01.y+d1.y,0.f)*w1.y
                 + fmaxf(e01.z+d1.z,0.f)*w1.z + fmaxf(e01.w+d1.w,0.f)*w1.w;
        float s1 = fmaxf(e10.x+d0.x,0.f)*w0.x + fmaxf(e10.y+d0.y,0.f)*w0.y
                 + fmaxf(e10.z+d0.z,0.f)*w0.z + fmaxf(e10.w+d0.w,0.f)*w0.w
                 + fmaxf(e11.x+d1.x,0.f)*w1.x + fmaxf(e11.y+d1.y,0.f)*w1.y
                 + fmaxf(e11.z+d1.z,0.f)*w1.z + fmaxf(e11.w+d1.w,0.f)*w1.w;
        #pragma unroll
        for (int o = 16; o; o >>= 1) {
            s0 += __shfl_xor_sync(0xffffffffu, s0, o);
            s1 += __shfl_xor_sync(0xffffffffu, s1, o);
        }
        if (l == 0) {
            g_scores[b*VV + v0] = s0;
            g_scores[b*VV + v1] = s1;
        }
    }
}

// ============================================================================
// K3: softmax over V -> write alphas[b,t,:], awe = alpha . enc, x = [emb, gate*awe]
// grid(64), block(512).  Length-masked.
// ============================================================================
__global__ void __launch_bounds__(512)
k3_attn(int t, const float* __restrict__ enc, const int* __restrict__ captions,
        const float* __restrict__ embW, const int* __restrict__ lens,
        float* __restrict__ out)
{
    int b = blockIdx.x;
    if (t >= lens[b]) return;
    int tid = threadIdx.x;
    __shared__ float s[VV];
    __shared__ float red[16*128];
    __shared__ float wmax[16], wsum[16], fin[2];
    int warp = tid >> 5, l = tid & 31;

    // load + max
    float m = -1e30f;
    for (int v = tid; v < VV; v += 512) { float x = g_scores[b*VV + v]; s[v] = x; m = fmaxf(m, x); }
    #pragma unroll
    for (int o = 16; o; o >>= 1) m = fmaxf(m, __shfl_xor_sync(0xffffffffu, m, o));
    if (l == 0) wmax[warp] = m;
    __syncthreads();
    if (tid == 0) {
        float mm = wmax[0];
        #pragma unroll
        for (int i = 1; i < 16; i++) mm = fmaxf(mm, wmax[i]);
        fin[0] = mm;
    }
    __syncthreads();
    float gmax = fin[0];

    // exp + sum
    float sum = 0.f;
    for (int v = tid; v < VV; v += 512) { float e = __expf(s[v] - gmax); s[v] = e; sum += e; }
    #pragma unroll
    for (int o = 16; o; o >>= 1) sum += __shfl_xor_sync(0xffffffffu, sum, o);
    if (l == 0) wsum[warp] = sum;
    __syncthreads();
    if (tid == 0) {
        float ss = 0.f;
        #pragma unroll
        for (int i = 0; i < 16; i++) ss += wsum[i];
        fin[1] = 1.f/ss;
    }
    __syncthreads();
    float inv = fin[1];

    float* aout = out + ALPHA_OFF + ((size_t)b*TT + t)*VV;
    for (int v = tid; v < VV; v += 512) { float a = s[v]*inv; s[v] = a; aout[v] = a; }
    __syncthreads();

    // awe: 16 v-rows x 32 lanes x float4 over ENC
    int vr = warp;
    float4 acc = make_float4(0.f,0.f,0.f,0.f);
    for (int v = vr; v < VV; v += 64) {
        #pragma unroll
        for (int u = 0; u < 4; u++) {
            int vv = v + u*16;
            float av = s[vv];
            float4 e = *(const float4*)&enc[((size_t)(b*VV + vv))*ENCD + l*4];
            acc.x += av*e.x; acc.y += av*e.y; acc.z += av*e.z; acc.w += av*e.w;
        }
    }
    *(float4*)&red[vr*128 + l*4] = acc;
    __syncthreads();
    if (tid < 128) {
        float aw = 0.f;
        #pragma unroll
        for (int i = 0; i < 16; i++) aw += red[i*128 + tid];
        aw *= g_gate[b*ENCD + tid];
        g_x[b*XD + EMBD + tid] = aw;
    }
    int cap = captions[b*TT + t];
    if (tid < EMBD) g_x[b*XD + tid] = embW[cap*EMBD + tid];
}

// ============================================================================
// K4: LSTM cell.  gates = [x,h] @ [W_ih,W_hh].T + b_ih + b_hh  (i,f,g,o)
// grid(64,2): 64 j-chunks (8 logical j -> 32 gate rows) x 2 b-halves (32 b).
// Weight row read once per b-half; z staged in smem k-tiles of 128.
// Ping-pong h update with per-b length mask (masked rows copied).
// ============================================================================
__global__ void __launch_bounds__(256)
k4_lstm(int t,
        const float* __restrict__ Wih, const float* __restrict__ bih,
        const float* __restrict__ Whh, const float* __restrict__ bhh,
        const int* __restrict__ lens)
{
    int jc = blockIdx.x;         // 0..63
    int bh = blockIdx.y;         // 0..1
    int tid = threadIdx.x;
    int p = t & 1;
    int jbase = jc*8;
    int b0 = bh*32;

    if (t >= lens[b0]) {         // lens sorted desc -> whole half masked
        int jj = tid >> 5, bl = tid & 31;
        int idx = (b0 + bl)*DECD + jbase + jj;
        g_hbuf[1-p][idx] = g_hbuf[p][idx];
        return;
    }

    __shared__ float zt[128*36];
    __shared__ float ws[32*132];
    __shared__ float gs[32*33];

    int r = tid >> 3;            // 0..31 gate-row within block
    int lane = tid & 7;
    int bl0 = lane*4;
    int grow = (r >> 3)*DECD + jbase + (r & 7);   // global gate row

    float acc0=0.f, acc1=0.f, acc2=0.f, acc3=0.f;
    const float* hsrc = g_hbuf[p];

    for (int kt = 0; kt < 7; kt++) {
        // z tile [128 k][32 b]
        for (int i = tid; i < 32*128; i += 256) {
            int bl = i >> 7, k = i & 127;
            float v;
            if (kt < 3) v = g_x[(b0 + bl)*XD + kt*128 + k];
            else        v = hsrc[(b0 + bl)*DECD + (kt-3)*128 + k];
            zt[k*36 + bl] = v;
        }
        // W tile [32 rows][128 k]
        const float* Wp = (kt < 3) ? Wih : Whh;
        int kstride = (kt < 3) ? XD : DECD;
        int kb = (kt < 3) ? kt*128 : (kt-3)*128;
        for (int i = tid; i < 32*128; i += 256) {
            int rr2 = i >> 7, k = i & 127;
            int gr = (rr2 >> 3)*DECD + jbase + (rr2 & 7);
            ws[rr2*132 + k] = Wp[(size_t)gr*kstride + kb + k];
        }
        __syncthreads();
        #pragma unroll 4
        for (int k = 0; k < 128; k += 4) {
            float4 w4 = *(const float4*)&ws[r*132 + k];
            float4 za = *(const float4*)&zt[(k  )*36 + bl0];
            float4 zb = *(const float4*)&zt[(k+1)*36 + bl0];
            float4 zc = *(const float4*)&zt[(k+2)*36 + bl0];
            float4 zd = *(const float4*)&zt[(k+3)*36 + bl0];
            acc0 += w4.x*za.x + w4.y*zb.x + w4.z*zc.x + w4.w*zd.x;
            acc1 += w4.x*za.y + w4.y*zb.y + w4.z*zc.y + w4.w*zd.y;
            acc2 += w4.x*za.z + w4.y*zb.z + w4.z*zc.z + w4.w*zd.z;
            acc3 += w4.x*za.w + w4.y*zb.w + w4.z*zc.w + w4.w*zd.w;
        }
        __syncthreads();
    }
    float bias = bih[grow] + bhh[grow];
    gs[r*33 + bl0 + 0] = acc0 + bias;
    gs[r*33 + bl0 + 1] = acc1 + bias;
    gs[r*33 + bl0 + 2] = acc2 + bias;
    gs[r*33 + bl0 + 3] = acc3 + bias;
    __syncthreads();

    {
        int jj = tid >> 5, bl = tid & 31;
        int b = b0 + bl;
        int hidx = b*DECD + jbase + jj;
        if (t < lens[b]) {
            float gi = gs[( 0 + jj)*33 + bl];
            float gf = gs[( 8 + jj)*33 + bl];
            float gg = gs[(16 + jj)*33 + bl];
            float go = gs[(24 + jj)*33 + bl];
            float si = sigf(gi), sf = sigf(gf), so = sigf(go);
            float tg = tanhf(gg);
            float cn = sf * g_c[hidx] + si * tg;
            float hn = so * tanhf(cn);
            g_c[hidx] = cn;
            g_hbuf[1-p][hidx] = hn;
        } else {
            g_hbuf[1-p][hidx] = g_hbuf[p][hidx];
        }
    }
}

// ============================================================================
extern "C" void kernel_launch(void* const* d_in, const int* in_sizes, int n_in,
                              void* d_out, int out_size)
{
    const float* enc      = (const float*)d_in[0];
    const int*   captions = (const int*)  d_in[1];
    const int*   lens     = (const int*)  d_in[2];
    const float* embW     = (const float*)d_in[3];
    const float* Wenc     = (const float*)d_in[4];
    const float* benc     = (const float*)d_in[5];
    const float* Wdec     = (const float*)d_in[6];
    const float* bdec     = (const float*)d_in[7];
    const float* wfull    = (const float*)d_in[8];
    // d_in[9] = b_full : dropped (softmax shift-invariant)
    const float* Wih      = (const float*)d_in[10];
    const float* bih      = (const float*)d_in[11];
    const float* Whh      = (const float*)d_in[12];
    const float* bhh      = (const float*)d_in[13];
    const float* Winith   = (const float*)d_in[14];
    const float* binith   = (const float*)d_in[15];
    const float* Winitc   = (const float*)d_in[16];
    const float* binitc   = (const float*)d_in[17];
    const float* Wbeta    = (const float*)d_in[18];
    const float* bbeta    = (const float*)d_in[19];
    const float* Wfin     = (const float*)d_in[20];
    const float* bfin     = (const float*)d_in[21];
    float* out = (float*)d_out;

    cudaFuncSetAttribute(s_encatt, cudaFuncAttributeMaxDynamicSharedMemorySize, EA_SMEM);

    // masked (b,t) slots stay zero; lengths written by s_init
    cudaMemsetAsync(d_out, 0, (size_t)out_size*sizeof(float), 0);

    s_init<<<BB, 512>>>(enc, lens, Winith, binith, Winitc, binitc, out);
    s_encatt<<<(BB*VV)/32, 256, EA_SMEM>>>(enc, Wenc, benc);

    for (int t = 0; t < TT; t++) {
        k1_head<<<dim3(26,4), 256>>>(t, Wdec, bdec, Wbeta, bbeta, Wfin, bfin, lens, out);
        k2_scores<<<dim3(16,64), 256>>>(t, wfull, lens);
        k3_attn<<<BB, 512>>>(t, enc, captions, embW, lens, out);
        k4_lstm<<<dim3(64,2), 256>>>(t, Wih, bih, Whh, bhh, lens);
    }
    // final predictions for t = T-1
    k1_head<<<dim3(26,4), 256>>>(TT, Wdec, bdec, Wbeta, bbeta, Wfin, bfin, lens, out);
}